// round 9
// baseline (speedup 1.0000x reference)
#include <cuda_runtime.h>
#include <cuda_bf16.h>
#include <cstdint>

// ============================================================================
// MajFC:  out = 1.125 * <X", W">, augmented ±1 vectors, K = 3072 + 1024 = 4096:
//   per 3-group, clip(sum,-1,1) = 0.5*(x0w0 + x1w1 + x2w2 - (x0x1x2)(w0w1w2)).
// R9: ±1 stored as INT8; GEMM on the (idle) tensor pipe via mma.sync s8 IMMA.
// K-split 8; s16-packed partials; combine fused via atomic finisher CTA.
// ============================================================================

#define BROWS 256
#define CIN   3072
#define COUT  1024
#define KBT   4096           // bytes per augmented row (3072 elem + 1024 prod)
#define NPO   (BROWS * COUT)
#define NSPLIT 8
#define KCB   (KBT / NSPLIT) // 512 bytes of K per split

__device__ __align__(16) signed char g_X8[BROWS * KBT];     // 1 MB
__device__ __align__(16) signed char g_W8[COUT  * KBT];     // 4 MB
__device__ __align__(16) short g_part[NSPLIT * NPO];        // 4 MB
__device__ int g_cnt[64];                                   // zero-init

// ---------------------------------------------------------------------------
// Pack to int8 ±1. One warp = 768 consecutive floats (256 groups) of one row.
// Lane: 6x LDG.128 -> 24 sign bytes + 8 product-sign bytes (W's negated).
// ---------------------------------------------------------------------------
#define SEGS 4
#define PACK_TASKS ((BROWS + COUT) * SEGS)       // 5120 warps

__global__ void __launch_bounds__(256) pack_kernel(const float* __restrict__ x,
                                                   const float* __restrict__ w) {
    int task = (blockIdx.x * blockDim.x + threadIdx.x) >> 5;
    int lane = threadIdx.x & 31;
    int row = task >> 2, seg = task & 3;

    const float* src;
    signed char* dst;
    unsigned flip;
    if (row < BROWS) {
        src = x + (size_t)row * CIN;
        dst = g_X8 + (size_t)row * KBT;
        flip = 0u;
    } else {
        src = w + (size_t)(row - BROWS) * CIN;
        dst = g_W8 + (size_t)(row - BROWS) * KBT;
        flip = 1u;                       // -prod(W) folded into the byte
    }

    const float4* p = reinterpret_cast<const float4*>(src + seg * 768 + lane * 24);
    float f[24];
#pragma unroll
    for (int j = 0; j < 6; j++) {
        float4 v = p[j];
        f[j * 4 + 0] = v.x; f[j * 4 + 1] = v.y;
        f[j * 4 + 2] = v.z; f[j * 4 + 3] = v.w;
    }
    unsigned b[24];
#pragma unroll
    for (int j = 0; j < 24; j++) b[j] = f[j] > 0.f;     // 1 = positive

    // element sign bytes: +1 -> 0x01, -1 -> 0xFF
    signed char* ed = dst + seg * 768 + lane * 24;
#pragma unroll
    for (int j = 0; j < 6; j++) {
        unsigned wd = 0;
#pragma unroll
        for (int e = 0; e < 4; e++) {
            unsigned byte = b[j * 4 + e] ? 0x01u : 0xFFu;
            wd |= byte << (8 * e);
        }
        *reinterpret_cast<unsigned*>(ed + j * 4) = wd;
    }
    // product sign bytes: prod>0 <=> #neg even <=> b0^b1^b2 == 1 (3 factors)
    unsigned pw0 = 0, pw1 = 0;
#pragma unroll
    for (int g = 0; g < 8; g++) {
        unsigned pos = b[3 * g] ^ b[3 * g + 1] ^ b[3 * g + 2] ^ flip;
        unsigned byte = pos ? 0x01u : 0xFFu;
        if (g < 4) pw0 |= byte << (8 * g);
        else       pw1 |= byte << (8 * (g - 4));
    }
    unsigned* pd = reinterpret_cast<unsigned*>(dst + CIN + seg * 256 + lane * 8);
    pd[0] = pw0; pd[1] = pw1;
}

// ---------------------------------------------------------------------------
// IMMA GEMM. CTA tile 64x64, 128 threads, 4 warps (warp tile 32x32),
// one 512-byte K chunk (2 staged sub-chunks of 256B). grid = (8, 16, 4).
// SMEM pitch 272B: ldmatrix rows hit distinct 16B banks (17 mod 8 = 1).
// ---------------------------------------------------------------------------
#define TM 64
#define TN 64
#define CHB 256
#define PITCH 272

__device__ __forceinline__ uint32_t smem_u32(const void* p) {
    return (uint32_t)__cvta_generic_to_shared(p);
}

__device__ __forceinline__ void ldsm4(unsigned* r, uint32_t addr) {
    asm volatile("ldmatrix.sync.aligned.m8n8.x4.shared.b16 {%0,%1,%2,%3}, [%4];"
                 : "=r"(r[0]), "=r"(r[1]), "=r"(r[2]), "=r"(r[3]) : "r"(addr));
}

__device__ __forceinline__ void mma_s8(int* d, const unsigned* a, const unsigned* b) {
    asm volatile(
        "mma.sync.aligned.m16n8k32.row.col.s32.s8.s8.s32 "
        "{%0,%1,%2,%3}, {%4,%5,%6,%7}, {%8,%9}, {%0,%1,%2,%3};"
        : "+r"(d[0]), "+r"(d[1]), "+r"(d[2]), "+r"(d[3])
        : "r"(a[0]), "r"(a[1]), "r"(a[2]), "r"(a[3]), "r"(b[0]), "r"(b[1]));
}

__global__ void __launch_bounds__(128) mma_gemm_kernel(float* __restrict__ out) {
    __shared__ __align__(16) unsigned char As[TM * PITCH];   // 17 KB
    __shared__ __align__(16) unsigned char Bs[TN * PITCH];   // 17 KB
    __shared__ int s_last;

    int tid = threadIdx.x, lane = tid & 31, wid = tid >> 5;
    int sp = blockIdx.x;                   // 8 (fastest: split CTAs adjacent)
    int n0 = blockIdx.y * TN;              // 16
    int m0 = blockIdx.z * TM;              // 4
    int tile = blockIdx.z * 16 + blockIdx.y;

    int wm = (wid >> 1) * 32, wn = (wid & 1) * 32;
    uint32_t asb = smem_u32(As), bsb = smem_u32(Bs);

    int acc[2][4][4] = {};                 // [m16-tile][n8-block][4]

    for (int ch = 0; ch < 2; ch++) {
        int kgb = sp * KCB + ch * CHB;
        // Stage A,B sub-chunks: 64 rows x 16 uint4 each; 8+8 uint4 per thread.
#pragma unroll
        for (int i = 0; i < 8; i++) {
            int idx = i * 128 + tid;
            int r = idx >> 4, c = (idx & 15) << 4;
            uint4 v = *reinterpret_cast<const uint4*>(
                g_X8 + (size_t)(m0 + r) * KBT + kgb + c);
            *reinterpret_cast<uint4*>(As + r * PITCH + c) = v;
        }
#pragma unroll
        for (int i = 0; i < 8; i++) {
            int idx = i * 128 + tid;
            int r = idx >> 4, c = (idx & 15) << 4;
            uint4 v = *reinterpret_cast<const uint4*>(
                g_W8 + (size_t)(n0 + r) * KBT + kgb + c);
            *reinterpret_cast<uint4*>(Bs + r * PITCH + c) = v;
        }
        __syncthreads();

#pragma unroll
        for (int ks = 0; ks < 8; ks++) {
            int kb = ks * 32;
            unsigned A0[4], A1[4], Bf[2][4];
            int t = lane >> 3, r = lane & 7;
            // A fragment tiles: t0=(r0-7,klo) t1=(r8-15,klo) t2=(r0-7,khi) t3=(r8-15,khi)
            uint32_t aad = asb + (uint32_t)((wm + (t & 1) * 8 + r) * PITCH
                                            + kb + (t >> 1) * 16);
            ldsm4(A0, aad);
            ldsm4(A1, aad + 16 * PITCH);
            // B fragment tiles: t0=(nlo,klo) t1=(nlo,khi) t2=(nhi,klo) t3=(nhi,khi)
            uint32_t bad = bsb + (uint32_t)((wn + (t >> 1) * 8 + r) * PITCH
                                            + kb + (t & 1) * 16);
            ldsm4(Bf[0], bad);
            ldsm4(Bf[1], bad + 16 * PITCH);
#pragma unroll
            for (int nb = 0; nb < 4; nb++) {
                const unsigned* bp = &Bf[nb >> 1][(nb & 1) * 2];
                mma_s8(acc[0][nb], A0, bp);
                mma_s8(acc[1][nb], A1, bp);
            }
        }
        __syncthreads();
    }

    // Partials: dot in [-512,512] -> two s16 packed per u32.
    short* gp = g_part + (size_t)sp * NPO;
#pragma unroll
    for (int mt = 0; mt < 2; mt++) {
#pragma unroll
        for (int nb = 0; nb < 4; nb++) {
            int m = m0 + wm + mt * 16 + (lane >> 2);
            int n = n0 + wn + nb * 8 + (lane & 3) * 2;
            int* a = acc[mt][nb];
            *reinterpret_cast<unsigned*>(&gp[(size_t)m * COUT + n]) =
                ((unsigned)a[0] & 0xFFFFu) | ((unsigned)a[1] << 16);
            *reinterpret_cast<unsigned*>(&gp[(size_t)(m + 8) * COUT + n]) =
                ((unsigned)a[2] & 0xFFFFu) | ((unsigned)a[3] << 16);
        }
    }

    // ---- fused combine: 8th-arriving split-CTA finishes the 64x64 tile ----
    __threadfence();
    __syncthreads();
    if (tid == 0) s_last = atomicAdd(&g_cnt[tile], 1);
    __syncthreads();
    if (s_last == NSPLIT - 1) {
        int fr = m0 + (tid >> 1);
        int fc = n0 + (tid & 1) * 32;
        size_t off = (size_t)fr * COUT + fc;
#pragma unroll
        for (int g = 0; g < 4; g++) {
            size_t o2 = off + g * 8;
            int s[8] = {0, 0, 0, 0, 0, 0, 0, 0};
#pragma unroll
            for (int q = 0; q < NSPLIT; q++) {
                uint4 v = *reinterpret_cast<const uint4*>(&g_part[(size_t)q * NPO + o2]);
                s[0] += (short)(v.x); s[1] += ((int)v.x) >> 16;
                s[2] += (short)(v.y); s[3] += ((int)v.y) >> 16;
                s[4] += (short)(v.z); s[5] += ((int)v.z) >> 16;
                s[6] += (short)(v.w); s[7] += ((int)v.w) >> 16;
            }
            float4 o0, o1;
            o0.x = 1.125f * s[0]; o0.y = 1.125f * s[1];
            o0.z = 1.125f * s[2]; o0.w = 1.125f * s[3];
            o1.x = 1.125f * s[4]; o1.y = 1.125f * s[5];
            o1.z = 1.125f * s[6]; o1.w = 1.125f * s[7];
            *reinterpret_cast<float4*>(&out[o2])     = o0;
            *reinterpret_cast<float4*>(&out[o2 + 4]) = o1;
        }
        if (tid == 0) g_cnt[tile] = 0;       // reset for next graph replay
    }
}

// ---------------------------------------------------------------------------
extern "C" void kernel_launch(void* const* d_in, const int* in_sizes, int n_in,
                              void* d_out, int out_size) {
    const float* x = (const float*)d_in[0];   // [256, 3072]
    const float* w = (const float*)d_in[1];   // [1024, 3072]
    float* out = (float*)d_out;               // [256, 1024] float32

    pack_kernel<<<PACK_TASKS * 32 / 256, 256>>>(x, w);

    dim3 grid(NSPLIT, COUT / TN, BROWS / TM); // (8, 16, 4) = 512 CTAs
    mma_gemm_kernel<<<grid, 128>>>(out);
}

// round 10
// speedup vs baseline: 1.8809x; 1.8809x over previous
#include <cuda_runtime.h>
#include <cuda_bf16.h>
#include <cstdint>

// ============================================================================
// MajFC:  out = 1.125 * <X", W">, augmented ±1 vectors, K = 3072 + 1024 = 4096:
//   per 3-group, clip(sum,-1,1) = 0.5*(x0w0 + x1w1 + x2w2 - (x0x1x2)(w0w1w2)).
// Bit-packed:  out = 4608 - 2.25 * popc(xbits ^ wbits)  over 128 words.
// R10: 4x4 thread tile + transposed W smem tile -> 2B smem/MAC, conflict-free.
// K-split 8; s16 partials; combine fused via atomic finisher CTA.
// ============================================================================

#define BROWS 256
#define CIN   3072
#define COUT  1024
#define KW    128            // 4096 bits per row
#define NSPLIT 8
#define KC    (KW / NSPLIT)  // 16 words per split
#define NPO   (BROWS * COUT)

__device__ __align__(16) uint32_t g_Xb[BROWS * KW];           // 128 KB
__device__ __align__(16) uint32_t g_Wb[COUT  * KW];           // 512 KB
__device__ __align__(16) short g_part[NSPLIT * NPO];          // 4 MB
__device__ int g_cnt[128];                                    // zero-init

// ---------------------------------------------------------------------------
// Pack (R8): one warp = 768 consecutive floats (256 groups) of one row.
// ---------------------------------------------------------------------------
#define SEGS 4
#define PACK_TASKS ((BROWS + COUT) * SEGS)       // 5120 warps

__global__ void __launch_bounds__(256) pack_kernel(const float* __restrict__ x,
                                                   const float* __restrict__ w) {
    int task = (blockIdx.x * blockDim.x + threadIdx.x) >> 5;
    int lane = threadIdx.x & 31;
    int row = task >> 2, seg = task & 3;

    const float* src;
    uint32_t*    dst;
    unsigned flip;
    if (row < BROWS) {
        src = x + (size_t)row * CIN;
        dst = g_Xb + (size_t)row * KW;
        flip = 0u;
    } else {
        src = w + (size_t)(row - BROWS) * CIN;
        dst = g_Wb + (size_t)(row - BROWS) * KW;
        flip = 1u;                       // -prod(W) folded into the bit
    }

    const float4* p = reinterpret_cast<const float4*>(src + seg * 768 + lane * 24);
    float f[24];
#pragma unroll
    for (int j = 0; j < 6; j++) {
        float4 v = p[j];
        f[j * 4 + 0] = v.x; f[j * 4 + 1] = v.y;
        f[j * 4 + 2] = v.z; f[j * 4 + 3] = v.w;
    }
    unsigned b[24];
#pragma unroll
    for (int j = 0; j < 24; j++) b[j] = f[j] > 0.f;

    unsigned myword = 0;
#pragma unroll
    for (int j = 0; j < 24; j++) {
        unsigned bw = __ballot_sync(0xFFFFFFFFu, b[j]);
        if (lane == j) myword = bw;
    }
#pragma unroll
    for (int g = 0; g < 8; g++) {
        unsigned pb = b[3 * g] ^ b[3 * g + 1] ^ b[3 * g + 2] ^ flip;
        unsigned bw = __ballot_sync(0xFFFFFFFFu, pb);
        if (lane == 24 + g) myword = bw;
    }

    if (lane < 24) dst[seg * 24 + lane]          = myword;
    else           dst[96 + seg * 8 + lane - 24] = myword;
}

// ---------------------------------------------------------------------------
// Binary GEMM: CTA tile 64(m) x 32(n) over one 16-word K chunk; 128 threads,
// thread tile 4x4. grid = (8, 32, 4) = 1024 CTAs.
// Xs: [64][20] pitch 80B (16B-aligned rows); compute reads are phase-broadcast.
// Ws: TRANSPOSED [k][n] = [16][32]; thread reads uint4 of 4 consecutive n ->
//     per-phase bank units = ni (0..7), conflict-free.
// ---------------------------------------------------------------------------
#define GM 64
#define GN 32
#define XSP 20

__global__ void __launch_bounds__(128) maj_gemm_kernel(float* __restrict__ out) {
    __shared__ __align__(16) uint32_t Xs[GM][XSP];   // 5 KB
    __shared__ __align__(16) uint32_t Ws[KC][GN];    // 2 KB
    __shared__ int s_last;

    int tid = threadIdx.x;
    int sp = blockIdx.x;                  // 8 (fastest: split CTAs adjacent)
    int n0 = blockIdx.y * GN;             // 32
    int m0 = blockIdx.z * GM;             // 4
    int tile = blockIdx.z * 32 + blockIdx.y;   // 0..127
    int k0 = sp * KC;

    // Stage X: 64 rows x 16 words = 256 uint4, 2 per thread (STS.128).
#pragma unroll
    for (int p = 0; p < 2; p++) {
        int idx = p * 128 + tid;
        int r = idx >> 2, c = (idx & 3) << 2;
        uint4 v = *reinterpret_cast<const uint4*>(&g_Xb[(size_t)(m0 + r) * KW + k0 + c]);
        *reinterpret_cast<uint4*>(&Xs[r][c]) = v;
    }
    // Stage W transposed: thread (n = tid&31, kq = tid>>5) reads 4 k-words of
    // row n, scatters to Ws[k][n]. STS.32 per j is 128B-contiguous across the
    // warp -> conflict-free.
    {
        int n = tid & 31, kq = tid >> 5;      // kq 0..3 -> k = 4kq..4kq+3
        uint4 v = *reinterpret_cast<const uint4*>(
            &g_Wb[(size_t)(n0 + n) * KW + k0 + kq * 4]);
        Ws[kq * 4 + 0][n] = v.x;
        Ws[kq * 4 + 1][n] = v.y;
        Ws[kq * 4 + 2][n] = v.z;
        Ws[kq * 4 + 3][n] = v.w;
    }
    __syncthreads();

    int mi = tid >> 3;                    // 0..15 -> m rows 4mi..4mi+3
    int ni = tid & 7;                     // 0..7  -> n cols 4ni..4ni+3

    int acc[4][4] = {};
#pragma unroll
    for (int ks = 0; ks < KC; ks += 4) {
        uint4 xr[4], wk[4];
#pragma unroll
        for (int r = 0; r < 4; r++)       // X: 4 m-rows, k-words ks..ks+3
            xr[r] = *reinterpret_cast<const uint4*>(&Xs[mi * 4 + r][ks]);
#pragma unroll
        for (int j = 0; j < 4; j++)       // W: k = ks+j, n cols 4ni..4ni+3
            wk[j] = *reinterpret_cast<const uint4*>(&Ws[ks + j][ni * 4]);
#pragma unroll
        for (int r = 0; r < 4; r++) {
            unsigned xw[4] = {xr[r].x, xr[r].y, xr[r].z, xr[r].w};
#pragma unroll
            for (int j = 0; j < 4; j++) {
                acc[r][0] += __popc(xw[j] ^ wk[j].x);
                acc[r][1] += __popc(xw[j] ^ wk[j].y);
                acc[r][2] += __popc(xw[j] ^ wk[j].z);
                acc[r][3] += __popc(xw[j] ^ wk[j].w);
            }
        }
    }

    // Partials: counts <= 512 -> s16, packed pairs (STG.64 per m-row).
    short* gp = g_part + (size_t)sp * NPO;
#pragma unroll
    for (int r = 0; r < 4; r++) {
        int m = m0 + mi * 4 + r, n = n0 + ni * 4;
        unsigned lo = ((unsigned)acc[r][0] & 0xFFFFu) | ((unsigned)acc[r][1] << 16);
        unsigned hi = ((unsigned)acc[r][2] & 0xFFFFu) | ((unsigned)acc[r][3] << 16);
        *reinterpret_cast<uint2*>(&gp[(size_t)m * COUT + n]) = make_uint2(lo, hi);
    }

    // ---- fused combine: 8th-arriving split-CTA finishes the 64x32 tile ----
    __threadfence();
    __syncthreads();
    if (tid == 0) s_last = atomicAdd(&g_cnt[tile], 1);
    __syncthreads();
    if (s_last == NSPLIT - 1) {
        // 2048 outputs, 16 per thread: m-row = tid>>1, 16-col half = tid&1.
        int fm = m0 + (tid >> 1);
        int fc = n0 + (tid & 1) * 16;
        size_t off = (size_t)fm * COUT + fc;
        int s[16] = {};
#pragma unroll
        for (int q = 0; q < NSPLIT; q++) {
            const short* pq = &g_part[(size_t)q * NPO + off];
#pragma unroll
            for (int h = 0; h < 2; h++) {
                uint4 v = *reinterpret_cast<const uint4*>(pq + h * 8);
                s[h * 8 + 0] += (short)(v.x); s[h * 8 + 1] += ((int)v.x) >> 16;
                s[h * 8 + 2] += (short)(v.y); s[h * 8 + 3] += ((int)v.y) >> 16;
                s[h * 8 + 4] += (short)(v.z); s[h * 8 + 5] += ((int)v.z) >> 16;
                s[h * 8 + 6] += (short)(v.w); s[h * 8 + 7] += ((int)v.w) >> 16;
            }
        }
#pragma unroll
        for (int g = 0; g < 4; g++) {
            float4 o;
            o.x = 4608.0f - 2.25f * (float)s[g * 4 + 0];
            o.y = 4608.0f - 2.25f * (float)s[g * 4 + 1];
            o.z = 4608.0f - 2.25f * (float)s[g * 4 + 2];
            o.w = 4608.0f - 2.25f * (float)s[g * 4 + 3];
            *reinterpret_cast<float4*>(&out[off + g * 4]) = o;
        }
        if (tid == 0) g_cnt[tile] = 0;    // reset for next graph replay
    }
}

// ---------------------------------------------------------------------------
extern "C" void kernel_launch(void* const* d_in, const int* in_sizes, int n_in,
                              void* d_out, int out_size) {
    const float* x = (const float*)d_in[0];   // [256, 3072]
    const float* w = (const float*)d_in[1];   // [1024, 3072]
    float* out = (float*)d_out;               // [256, 1024] float32

    pack_kernel<<<PACK_TASKS * 32 / 256, 256>>>(x, w);

    dim3 grid(NSPLIT, COUT / GN, BROWS / GM); // (8, 32, 4) = 1024 CTAs
    maj_gemm_kernel<<<grid, 128>>>(out);
}

// round 11
// speedup vs baseline: 2.1205x; 1.1274x over previous
#include <cuda_runtime.h>
#include <cuda_bf16.h>
#include <cstdint>

// ============================================================================
// MajFC:  out = 1.125 * <X", W">, augmented ±1 vectors, K = 3072 + 1024 = 4096:
//   per 3-group, clip(sum,-1,1) = 0.5*(x0w0 + x1w1 + x2w2 - (x0x1x2)(w0w1w2)).
// Bit-packed:  out = 4608 - 2.25 * popc(xbits ^ wbits)  over 128 words.
// R11: Harley-Seal CSA compression -> 5 POPC per 16 words (POPC pipe is the
// measured quarter-rate bottleneck). K-split 8; fused atomic-finisher combine.
// ============================================================================

#define BROWS 256
#define CIN   3072
#define COUT  1024
#define KW    128            // 4096 bits per row
#define NSPLIT 8
#define KC    (KW / NSPLIT)  // 16 words per split
#define NPO   (BROWS * COUT)

__device__ __align__(16) uint32_t g_Xb[BROWS * KW];           // 128 KB
__device__ __align__(16) uint32_t g_Wb[COUT  * KW];           // 512 KB
__device__ __align__(16) short g_part[NSPLIT * NPO];          // 4 MB
__device__ int g_cnt[256];                                    // zero-init

// ---------------------------------------------------------------------------
// Pack (R8): one warp = 768 consecutive floats (256 groups) of one row.
// ---------------------------------------------------------------------------
#define SEGS 4
#define PACK_TASKS ((BROWS + COUT) * SEGS)       // 5120 warps

__global__ void __launch_bounds__(256) pack_kernel(const float* __restrict__ x,
                                                   const float* __restrict__ w) {
    int task = (blockIdx.x * blockDim.x + threadIdx.x) >> 5;
    int lane = threadIdx.x & 31;
    int row = task >> 2, seg = task & 3;

    const float* src;
    uint32_t*    dst;
    unsigned flip;
    if (row < BROWS) {
        src = x + (size_t)row * CIN;
        dst = g_Xb + (size_t)row * KW;
        flip = 0u;
    } else {
        src = w + (size_t)(row - BROWS) * CIN;
        dst = g_Wb + (size_t)(row - BROWS) * KW;
        flip = 1u;                       // -prod(W) folded into the bit
    }

    const float4* p = reinterpret_cast<const float4*>(src + seg * 768 + lane * 24);
    float f[24];
#pragma unroll
    for (int j = 0; j < 6; j++) {
        float4 v = p[j];
        f[j * 4 + 0] = v.x; f[j * 4 + 1] = v.y;
        f[j * 4 + 2] = v.z; f[j * 4 + 3] = v.w;
    }
    unsigned b[24];
#pragma unroll
    for (int j = 0; j < 24; j++) b[j] = f[j] > 0.f;

    unsigned myword = 0;
#pragma unroll
    for (int j = 0; j < 24; j++) {
        unsigned bw = __ballot_sync(0xFFFFFFFFu, b[j]);
        if (lane == j) myword = bw;
    }
#pragma unroll
    for (int g = 0; g < 8; g++) {
        unsigned pb = b[3 * g] ^ b[3 * g + 1] ^ b[3 * g + 2] ^ flip;
        unsigned bw = __ballot_sync(0xFFFFFFFFu, pb);
        if (lane == 24 + g) myword = bw;
    }

    if (lane < 24) dst[seg * 24 + lane]          = myword;
    else           dst[96 + seg * 8 + lane - 24] = myword;
}

// ---------------------------------------------------------------------------
// Carry-save adder: single-LOP3 majority (carry) + single-LOP3 xor3 (sum).
// Inputs by value -> aliasing-safe when h/l overwrite state.
// ---------------------------------------------------------------------------
__device__ __forceinline__ void csa(uint32_t& h, uint32_t& l,
                                    uint32_t a, uint32_t b, uint32_t c) {
    uint32_t hh, ll;
    asm("lop3.b32 %0, %1, %2, %3, 0xE8;" : "=r"(hh) : "r"(a), "r"(b), "r"(c));
    asm("lop3.b32 %0, %1, %2, %3, 0x96;" : "=r"(ll) : "r"(a), "r"(b), "r"(c));
    h = hh; l = ll;
}

// Harley-Seal popcount of (xw[i] ^ ww[i]) over 16 words: 5 POPC total.
__device__ __forceinline__ int hs16(const uint32_t* __restrict__ xw,
                                    const uint32_t* __restrict__ ww) {
    uint32_t ones = 0, twos = 0, fours = 0;
    int cnt8 = 0;
#pragma unroll
    for (int b = 0; b < 2; b++) {
        uint32_t w0 = xw[b * 8 + 0] ^ ww[b * 8 + 0];
        uint32_t w1 = xw[b * 8 + 1] ^ ww[b * 8 + 1];
        uint32_t w2 = xw[b * 8 + 2] ^ ww[b * 8 + 2];
        uint32_t w3 = xw[b * 8 + 3] ^ ww[b * 8 + 3];
        uint32_t w4 = xw[b * 8 + 4] ^ ww[b * 8 + 4];
        uint32_t w5 = xw[b * 8 + 5] ^ ww[b * 8 + 5];
        uint32_t w6 = xw[b * 8 + 6] ^ ww[b * 8 + 6];
        uint32_t w7 = xw[b * 8 + 7] ^ ww[b * 8 + 7];
        uint32_t tA, tB, fA, fB, e;
        csa(tA, ones, ones, w0, w1);
        csa(tB, ones, ones, w2, w3);
        csa(fA, twos, twos, tA, tB);
        csa(tA, ones, ones, w4, w5);
        csa(tB, ones, ones, w6, w7);
        csa(fB, twos, twos, tA, tB);
        csa(e,  fours, fours, fA, fB);
        cnt8 += __popc(e);
    }
    return 8 * cnt8 + 4 * __popc(fours) + 2 * __popc(twos) + __popc(ones);
}

// ---------------------------------------------------------------------------
// Binary GEMM: CTA tile 32(m) x 32(n), one 16-word K chunk, 128 threads,
// thread tile 2m x 4n (n strided by 8 for conflict-free Ws reads with
// pitch 20 words: ni*5 mod 8 is a permutation). grid = (8, 32, 8) = 2048 CTAs.
// ---------------------------------------------------------------------------
#define GT 32
#define SPW 20

__global__ void __launch_bounds__(128) maj_gemm_kernel(float* __restrict__ out) {
    __shared__ __align__(16) uint32_t Xs[GT][SPW];   // 2.5 KB
    __shared__ __align__(16) uint32_t Ws[GT][SPW];   // 2.5 KB
    __shared__ int s_last;

    int tid = threadIdx.x;
    int sp = blockIdx.x;                  // 8 (fastest: split CTAs adjacent)
    int n0 = blockIdx.y * GT;             // 32
    int m0 = blockIdx.z * GT;             // 8
    int tile = blockIdx.z * 32 + blockIdx.y;   // 0..255
    int k0 = sp * KC;

    // Stage X+W: 64 rows x 16 words = 256 uint4, 2 per thread.
#pragma unroll
    for (int p = 0; p < 2; p++) {
        int idx = p * 128 + tid;
        int r = idx >> 2, c = (idx & 3) << 2;
        const uint32_t* src = (r < GT)
            ? &g_Xb[(size_t)(m0 + r) * KW + k0 + c]
            : &g_Wb[(size_t)(n0 + r - GT) * KW + k0 + c];
        uint4 v = *reinterpret_cast<const uint4*>(src);
        uint32_t* d = (r < GT) ? &Xs[r][c] : &Ws[r - GT][c];
        *reinterpret_cast<uint4*>(d) = v;
    }
    __syncthreads();

    int mi = tid >> 3;                    // 0..15 -> m rows 2mi, 2mi+1
    int ni = tid & 7;                     // 0..7  -> n cols ni, ni+8, ni+16, ni+24

    // X rows held in registers for the whole split (broadcast LDS.128).
    uint32_t xw[2][16];
#pragma unroll
    for (int r = 0; r < 2; r++)
#pragma unroll
        for (int q = 0; q < 4; q++) {
            uint4 v = *reinterpret_cast<const uint4*>(&Xs[mi * 2 + r][q * 4]);
            xw[r][q * 4 + 0] = v.x; xw[r][q * 4 + 1] = v.y;
            xw[r][q * 4 + 2] = v.z; xw[r][q * 4 + 3] = v.w;
        }

    int acc[2][4];
#pragma unroll
    for (int c = 0; c < 4; c++) {
        uint32_t wv[16];
#pragma unroll
        for (int q = 0; q < 4; q++) {
            uint4 v = *reinterpret_cast<const uint4*>(&Ws[ni + c * 8][q * 4]);
            wv[q * 4 + 0] = v.x; wv[q * 4 + 1] = v.y;
            wv[q * 4 + 2] = v.z; wv[q * 4 + 3] = v.w;
        }
        acc[0][c] = hs16(xw[0], wv);
        acc[1][c] = hs16(xw[1], wv);
    }

    // Partials: counts <= 512 -> s16.
    short* gp = g_part + (size_t)sp * NPO;
#pragma unroll
    for (int r = 0; r < 2; r++) {
        int m = m0 + mi * 2 + r;
#pragma unroll
        for (int c = 0; c < 4; c++)
            gp[(size_t)m * COUT + n0 + ni + c * 8] = (short)acc[r][c];
    }

    // ---- fused combine: 8th-arriving split-CTA finishes the 32x32 tile ----
    __threadfence();
    __syncthreads();
    if (tid == 0) s_last = atomicAdd(&g_cnt[tile], 1);
    __syncthreads();
    if (s_last == NSPLIT - 1) {
        // 1024 outputs, 8 per thread: row = tid>>2, col-octet = (tid&3)*8.
        int fm = m0 + (tid >> 2);
        int fc = n0 + (tid & 3) * 8;
        size_t off = (size_t)fm * COUT + fc;
        int s[8] = {};
#pragma unroll
        for (int q = 0; q < NSPLIT; q++) {
            uint4 v = *reinterpret_cast<const uint4*>(&g_part[(size_t)q * NPO + off]);
            s[0] += (short)(v.x); s[1] += ((int)v.x) >> 16;
            s[2] += (short)(v.y); s[3] += ((int)v.y) >> 16;
            s[4] += (short)(v.z); s[5] += ((int)v.z) >> 16;
            s[6] += (short)(v.w); s[7] += ((int)v.w) >> 16;
        }
#pragma unroll
        for (int g = 0; g < 2; g++) {
            float4 o;
            o.x = 4608.0f - 2.25f * (float)s[g * 4 + 0];
            o.y = 4608.0f - 2.25f * (float)s[g * 4 + 1];
            o.z = 4608.0f - 2.25f * (float)s[g * 4 + 2];
            o.w = 4608.0f - 2.25f * (float)s[g * 4 + 3];
            *reinterpret_cast<float4*>(&out[off + g * 4]) = o;
        }
        if (tid == 0) g_cnt[tile] = 0;    // reset for next graph replay
    }
}

// ---------------------------------------------------------------------------
extern "C" void kernel_launch(void* const* d_in, const int* in_sizes, int n_in,
                              void* d_out, int out_size) {
    const float* x = (const float*)d_in[0];   // [256, 3072]
    const float* w = (const float*)d_in[1];   // [1024, 3072]
    float* out = (float*)d_out;               // [256, 1024] float32

    pack_kernel<<<PACK_TASKS * 32 / 256, 256>>>(x, w);

    dim3 grid(NSPLIT, COUT / GT, BROWS / GT); // (8, 32, 8) = 2048 CTAs
    maj_gemm_kernel<<<grid, 128>>>(out);
}

// round 12
// speedup vs baseline: 2.3028x; 1.0860x over previous
#include <cuda_runtime.h>
#include <cuda_bf16.h>
#include <cstdint>

// ============================================================================
// MajFC via bit-plane majority. Per 3-group with mismatch bits m = xb ^ wb:
//   clip(sum, -1, 1) = 1 - 2*MAJ(m0, m1, m2)
//   out = 2.25 * (1024 - 2*T) = 2304 - 4.5*T,   T = #groups with MAJ=1.
// Rows stored as 3 bit-planes (32 groups/word): 32 groups cost only
// 3 XOR + 1 LOP3 + 1 POPC + 1 ADD. K = 96 words. K-split 8; fused finisher.
// ============================================================================

#define BROWS 256
#define CIN   3072
#define COUT  1024
#define KWP   96             // 3 planes x 32 block-words per row
#define NSPLIT 8
#define KCW   12             // words per split = 4 blocks x 3 planes
#define NPO   (BROWS * COUT)

// Row layout: 8 supergroups of 12 words; supergroup s (blocks 4s..4s+3):
//   words [s*12 + j*4 + e] = plane j of block 4s+e.
__device__ __align__(16) uint32_t g_Xb[BROWS * KWP];          // 96 KB
__device__ __align__(16) uint32_t g_Wb[COUT  * KWP];          // 384 KB
__device__ __align__(16) short g_part[NSPLIT * NPO];          // 4 MB
__device__ int g_cnt[256];                                    // zero-init

// ---------------------------------------------------------------------------
// Pack: one warp = 768 floats (256 groups = 8 blocks) of one row.
// Lane i owns group (block*32 + i) of each block: 3 scalar loads per block.
// 24 ballots -> 24 plane words; lanes 0..23 store one word each.
// ---------------------------------------------------------------------------
#define SEGS 4
#define PACK_TASKS ((BROWS + COUT) * SEGS)       // 5120 warps

__global__ void __launch_bounds__(256) pack_kernel(const float* __restrict__ x,
                                                   const float* __restrict__ w) {
    int task = (blockIdx.x * blockDim.x + threadIdx.x) >> 5;
    int lane = threadIdx.x & 31;
    int row = task >> 2, seg = task & 3;

    const float* src;
    uint32_t*    dst;
    if (row < BROWS) {
        src = x + (size_t)row * CIN;
        dst = g_Xb + (size_t)row * KWP;
    } else {
        src = w + (size_t)(row - BROWS) * CIN;
        dst = g_Wb + (size_t)(row - BROWS) * KWP;
    }
    const float* base = src + seg * 768 + lane * 3;

    unsigned c0[8], c1[8], c2[8];
#pragma unroll
    for (int b = 0; b < 8; b++) {
        const float* p = base + b * 96;
        c0[b] = p[0] > 0.f;
        c1[b] = p[1] > 0.f;
        c2[b] = p[2] > 0.f;
    }

    unsigned my = 0;
#pragma unroll
    for (int b = 0; b < 8; b++) {
        unsigned w0 = __ballot_sync(0xFFFFFFFFu, c0[b]);
        unsigned w1 = __ballot_sync(0xFFFFFFFFu, c1[b]);
        unsigned w2 = __ballot_sync(0xFFFFFFFFu, c2[b]);
        if (lane == b)      my = w0;
        if (lane == 8 + b)  my = w1;
        if (lane == 16 + b) my = w2;
    }

    if (lane < 24) {
        int j = lane >> 3, bl = lane & 7;       // plane, local block
        int gb = seg * 8 + bl;                  // global block 0..31
        dst[(gb >> 2) * 12 + j * 4 + (gb & 3)] = my;
    }
}

// ---------------------------------------------------------------------------
// Majority-count GEMM: CTA tile 32(m) x 32(n), one 12-word split (4 blocks),
// 128 threads, thread tile 2m x 4n (n strided by 8). grid = (8, 32, 8).
// Pitch 12 words (48B): rows 16B-aligned; W-read units 3*ni mod 8 = perm ->
// conflict-free; X-reads phase-broadcast.
// ---------------------------------------------------------------------------
#define GT 32

__device__ __forceinline__ uint32_t maj3(uint32_t a, uint32_t b, uint32_t c) {
    uint32_t r;
    asm("lop3.b32 %0, %1, %2, %3, 0xE8;" : "=r"(r) : "r"(a), "r"(b), "r"(c));
    return r;
}

__global__ void __launch_bounds__(128) maj_gemm_kernel(float* __restrict__ out) {
    __shared__ __align__(16) uint32_t Xs[GT][KCW];   // 1.5 KB
    __shared__ __align__(16) uint32_t Ws[GT][KCW];   // 1.5 KB
    __shared__ int s_last;

    int tid = threadIdx.x;
    int sp = blockIdx.x;                  // 8 (fastest: split CTAs adjacent)
    int n0 = blockIdx.y * GT;             // 32
    int m0 = blockIdx.z * GT;             // 8
    int tile = blockIdx.z * 32 + blockIdx.y;   // 0..255
    int k0 = sp * KCW;

    // Stage X+W: 64 rows x 3 uint4 = 192 uint4; threads 0..127 do 1-2 each.
#pragma unroll
    for (int p = 0; p < 2; p++) {
        int idx = p * 128 + tid;
        if (idx < 192) {
            int r = idx / 3, q = idx - r * 3;
            const uint32_t* src = (r < GT)
                ? &g_Xb[(size_t)(m0 + r) * KWP + k0 + q * 4]
                : &g_Wb[(size_t)(n0 + r - GT) * KWP + k0 + q * 4];
            uint4 v = *reinterpret_cast<const uint4*>(src);
            uint32_t* d = (r < GT) ? &Xs[r][q * 4] : &Ws[r - GT][q * 4];
            *reinterpret_cast<uint4*>(d) = v;
        }
    }
    __syncthreads();

    int mi = tid >> 3;                    // 0..15 -> m rows 2mi, 2mi+1
    int ni = tid & 7;                     // 0..7  -> n cols ni+8c

    // X split (2 rows x 12 words) in registers; q=0/1/2 are planes 0/1/2.
    uint4 xp[2][3];
#pragma unroll
    for (int r = 0; r < 2; r++)
#pragma unroll
        for (int q = 0; q < 3; q++)
            xp[r][q] = *reinterpret_cast<const uint4*>(&Xs[mi * 2 + r][q * 4]);

    int acc[2][4];
#pragma unroll
    for (int c = 0; c < 4; c++) {
        uint4 wp0 = *reinterpret_cast<const uint4*>(&Ws[ni + c * 8][0]);
        uint4 wp1 = *reinterpret_cast<const uint4*>(&Ws[ni + c * 8][4]);
        uint4 wp2 = *reinterpret_cast<const uint4*>(&Ws[ni + c * 8][8]);
        const uint32_t* w0 = reinterpret_cast<const uint32_t*>(&wp0);
        const uint32_t* w1 = reinterpret_cast<const uint32_t*>(&wp1);
        const uint32_t* w2 = reinterpret_cast<const uint32_t*>(&wp2);
#pragma unroll
        for (int r = 0; r < 2; r++) {
            const uint32_t* x0 = reinterpret_cast<const uint32_t*>(&xp[r][0]);
            const uint32_t* x1 = reinterpret_cast<const uint32_t*>(&xp[r][1]);
            const uint32_t* x2 = reinterpret_cast<const uint32_t*>(&xp[r][2]);
            int a = 0;
#pragma unroll
            for (int e = 0; e < 4; e++) {
                uint32_t m0w = x0[e] ^ w0[e];
                uint32_t m1w = x1[e] ^ w1[e];
                uint32_t m2w = x2[e] ^ w2[e];
                a += __popc(maj3(m0w, m1w, m2w));
            }
            acc[r][c] = a;
        }
    }

    // Partials: T per split <= 128 -> s16.
    short* gp = g_part + (size_t)sp * NPO;
#pragma unroll
    for (int r = 0; r < 2; r++) {
        int m = m0 + mi * 2 + r;
#pragma unroll
        for (int c = 0; c < 4; c++)
            gp[(size_t)m * COUT + n0 + ni + c * 8] = (short)acc[r][c];
    }

    // ---- fused combine: 8th-arriving split-CTA finishes the 32x32 tile ----
    __threadfence();
    __syncthreads();
    if (tid == 0) s_last = atomicAdd(&g_cnt[tile], 1);
    __syncthreads();
    if (s_last == NSPLIT - 1) {
        // 1024 outputs, 8 per thread: row = tid>>2, col-octet = (tid&3)*8.
        int fm = m0 + (tid >> 2);
        int fc = n0 + (tid & 3) * 8;
        size_t off = (size_t)fm * COUT + fc;
        int s[8] = {};
#pragma unroll
        for (int q = 0; q < NSPLIT; q++) {
            uint4 v = *reinterpret_cast<const uint4*>(&g_part[(size_t)q * NPO + off]);
            s[0] += (short)(v.x); s[1] += ((int)v.x) >> 16;
            s[2] += (short)(v.y); s[3] += ((int)v.y) >> 16;
            s[4] += (short)(v.z); s[5] += ((int)v.z) >> 16;
            s[6] += (short)(v.w); s[7] += ((int)v.w) >> 16;
        }
        // out = 2.25 * (1024 - 2T) = 2304 - 4.5*T
#pragma unroll
        for (int g = 0; g < 2; g++) {
            float4 o;
            o.x = 2304.0f - 4.5f * (float)s[g * 4 + 0];
            o.y = 2304.0f - 4.5f * (float)s[g * 4 + 1];
            o.z = 2304.0f - 4.5f * (float)s[g * 4 + 2];
            o.w = 2304.0f - 4.5f * (float)s[g * 4 + 3];
            *reinterpret_cast<float4*>(&out[off + g * 4]) = o;
        }
        if (tid == 0) g_cnt[tile] = 0;    // reset for next graph replay
    }
}

// ---------------------------------------------------------------------------
extern "C" void kernel_launch(void* const* d_in, const int* in_sizes, int n_in,
                              void* d_out, int out_size) {
    const float* x = (const float*)d_in[0];   // [256, 3072]
    const float* w = (const float*)d_in[1];   // [1024, 3072]
    float* out = (float*)d_out;               // [256, 1024] float32

    pack_kernel<<<PACK_TASKS * 32 / 256, 256>>>(x, w);

    dim3 grid(NSPLIT, COUT / GT, BROWS / GT); // (8, 32, 8) = 2048 CTAs
    maj_gemm_kernel<<<grid, 128>>>(out);
}